// round 15
// baseline (speedup 1.0000x reference)
#include <cuda_runtime.h>
#include <cuda_fp16.h>
#include <math.h>
#include <stdint.h>

// ---------------- problem constants ----------------
#define L_TOK   4096
#define DMODEL  3584
#define NH      112
#define HD      64
#define DS      64
#define CHUNKSZ 128
#define NCHUNK  32
#define NG      2
#define HPG     (NH / NG)          // 56
#define INNER   (NH * HD)          // 7168
#define IN2     (2 * INNER)        // 14336

// ---------------- scratch (device globals; no cudaMalloc allowed) ----------
__device__ float  g_xz[(size_t)L_TOK * IN2];           // [x | z]  (fp32)
__device__ __half g_ygh[(size_t)L_TOK * INNER];        // gated y  (fp16)
__device__ float  g_states[(size_t)NCHUNK * NH * HD * DS];  // [k][h][p][n]
__device__ __align__(16) __half g_prevh[(size_t)NCHUNK * NH * HD * DS]; // fp16 [p][n]
__device__ __align__(16) __half g_G[(size_t)NCHUNK * NG * CHUNKSZ * CHUNKSZ];
__device__ __half g_hidh[(size_t)L_TOK * DMODEL];
__device__ __half g_w1h[(size_t)IN2 * DMODEL];
__device__ __half g_w2h[(size_t)DMODEL * INNER];
__device__ __half g_Bh[(size_t)L_TOK * NG * DS];
__device__ __half g_Ch[(size_t)L_TOK * NG * DS];
__device__ float  g_dt[NH];
__device__ float  g_a[NH];

// ---------------- helpers ---------------------------------------------------
__device__ __forceinline__ uint32_t s2u(const void* p) {
    uint32_t a;
    asm("{ .reg .u64 t; cvta.to.shared.u64 t, %1; cvt.u32.u64 %0, t; }"
        : "=r"(a) : "l"(p));
    return a;
}
__device__ __forceinline__ void cpasync16(uint32_t saddr, const void* g) {
    asm volatile("cp.async.cg.shared.global [%0], [%1], 16;" :: "r"(saddr), "l"(g));
}
__device__ __forceinline__ void ldsm4(uint32_t* r, uint32_t addr) {
    asm volatile("ldmatrix.sync.aligned.m8n8.x4.shared.b16 {%0,%1,%2,%3}, [%4];"
                 : "=r"(r[0]), "=r"(r[1]), "=r"(r[2]), "=r"(r[3]) : "r"(addr));
}
__device__ __forceinline__ void mma16n8k16(float* d, const uint32_t* a,
                                           uint32_t b0, uint32_t b1) {
    asm volatile(
        "mma.sync.aligned.m16n8k16.row.col.f32.f16.f16.f32 "
        "{%0,%1,%2,%3}, {%4,%5,%6,%7}, {%8,%9}, {%0,%1,%2,%3};"
        : "+f"(d[0]), "+f"(d[1]), "+f"(d[2]), "+f"(d[3])
        : "r"(a[0]), "r"(a[1]), "r"(a[2]), "r"(a[3]), "r"(b0), "r"(b1));
}
__device__ __forceinline__ uint32_t pack_h2(float lo, float hi) {
    uint32_t r;
    asm("cvt.rn.f16x2.f32 %0, %1, %2;" : "=r"(r) : "f"(hi), "f"(lo));
    return r;
}

// ---------------- per-head parameters --------------------------------------
__global__ void hparams_kernel(const float* __restrict__ A_log,
                               const float* __restrict__ dt_bias) {
    int h = threadIdx.x;
    if (h < NH) {
        float xv = 0.1f + dt_bias[h];
        float sp = (xv > 20.f) ? xv : log1pf(expf(xv));
        g_dt[h] = sp;
        g_a[h]  = -expf(A_log[h]) * sp;
    }
}

// ---------------- fp32 -> fp16 conversion ----------------------------------
__global__ void to_half_kernel(const float* __restrict__ in, __half* __restrict__ out, int n8) {
    int i = blockIdx.x * blockDim.x + threadIdx.x;
    int stride = gridDim.x * blockDim.x;
    for (; i < n8; i += stride) {
        float4 a = ((const float4*)in)[2 * i];
        float4 b = ((const float4*)in)[2 * i + 1];
        uint4 o;
        o.x = pack_h2(a.x, a.y);
        o.y = pack_h2(a.z, a.w);
        o.z = pack_h2(b.x, b.y);
        o.w = pack_h2(b.z, b.w);
        ((uint4*)out)[i] = o;
    }
}

// ---------------- FP16 GEMM: 128x256 tile, KTH=128, 2-stage double buffer --
#define KTH      128
#define ALDH     136                         // halfs; 272B row (17x16B, conflict-free)
#define A_H      (128 * ALDH)                // halfs
#define B_H      (256 * ALDH)
#define STGB     ((A_H + B_H) * 2)           // 104448 B / stage
#define NSTG     2
#define GM_SMEM  (NSTG * STGB)               // 208896 B

__global__ __launch_bounds__(512, 1)
void gemm_mma(const __half* __restrict__ A, const __half* __restrict__ B,
              float* __restrict__ C, int M, int N, int K, int tiles_m) {
    extern __shared__ __align__(16) char smraw[];
    uint32_t sbase = s2u(smraw);

    int tid = threadIdx.x, lane = tid & 31, wid = tid >> 5;
    int wm = (wid & 1) * 64;
    int wn = (wid >> 1) * 32;
    int bid = blockIdx.x;
    int m0 = (bid % tiles_m) * 128;
    int n0 = (bid / tiles_m) * 256;

    // cp.async: A 128x128 halfs = 2048 16B vectors (4/thread), B 256x128 = 4096 (8/thread)
    int r0l = tid >> 4, c8l = (tid & 15) * 8;
    const __half* gA0 = A + (size_t)(m0 + r0l) * K + c8l;
    const __half* gB0 = B + (size_t)(n0 + r0l) * K + c8l;
    uint32_t oA0 = sbase + (uint32_t)(r0l * ALDH + c8l) * 2;
    uint32_t oB0 = sbase + (uint32_t)(A_H + r0l * ALDH + c8l) * 2;
    const size_t gstep = (size_t)32 * K;         // 32 rows per it
    const uint32_t ostep = 32 * ALDH * 2;

    int lr = lane & 7;
    int a_row = lr + ((lane >> 3) & 1) * 8;
    int a_col = ((lane >> 4) & 1) * 8;
    uint32_t aoff[4];
    #pragma unroll
    for (int t = 0; t < 4; t++)
        aoff[t] = sbase + (uint32_t)(((wm + t * 16 + a_row) * ALDH + a_col) * 2);
    int b_row = lr + ((lane >> 4) & 1) * 8;
    int b_col = ((lane >> 3) & 1) * 8;
    uint32_t boff[2];
    #pragma unroll
    for (int v = 0; v < 2; v++)
        boff[v] = sbase + (uint32_t)((A_H + (wn + v * 16 + b_row) * ALDH + b_col) * 2);

    const int NKC = K / KTH;

    // prologue: stage 0
    #pragma unroll
    for (int it = 0; it < 4; it++)
        cpasync16(oA0 + it * ostep, gA0 + it * gstep);
    #pragma unroll
    for (int it = 0; it < 8; it++)
        cpasync16(oB0 + it * ostep, gB0 + it * gstep);
    asm volatile("cp.async.commit_group;");

    float acc[4][4][4];
    #pragma unroll
    for (int t = 0; t < 4; t++)
        #pragma unroll
        for (int u = 0; u < 4; u++)
            #pragma unroll
            for (int v = 0; v < 4; v++) acc[t][u][v] = 0.f;

    for (int kb = 0; kb < NKC; kb++) {
        // guard: all warps finished reading the buffer we are about to overwrite
        __syncthreads();
        {
            int fc = kb + 1;
            if (fc < NKC) {
                uint32_t sb = (uint32_t)((fc & 1) * STGB);
                #pragma unroll
                for (int it = 0; it < 4; it++)
                    cpasync16(sb + oA0 + it * ostep, gA0 + it * gstep + fc * KTH);
                #pragma unroll
                for (int it = 0; it < 8; it++)
                    cpasync16(sb + oB0 + it * ostep, gB0 + it * gstep + fc * KTH);
            }
            asm volatile("cp.async.commit_group;");
        }
        asm volatile("cp.async.wait_group 1;");
        __syncthreads();

        uint32_t stb = (uint32_t)((kb & 1) * STGB);
        #pragma unroll
        for (int ks = 0; ks < 8; ks++) {
            uint32_t kadd = stb + ks * 32;       // 16 halfs per k-step
            uint32_t af[4][4];
            #pragma unroll
            for (int t = 0; t < 4; t++) ldsm4(af[t], aoff[t] + kadd);
            uint32_t bf[2][4];
            #pragma unroll
            for (int v = 0; v < 2; v++) ldsm4(bf[v], boff[v] + kadd);
            #pragma unroll
            for (int u = 0; u < 4; u++) {
                uint32_t b0 = bf[u >> 1][(u & 1) * 2 + 0];
                uint32_t b1 = bf[u >> 1][(u & 1) * 2 + 1];
                #pragma unroll
                for (int t = 0; t < 4; t++) mma16n8k16(acc[t][u], af[t], b0, b1);
            }
        }
    }

    int g4 = lane >> 2, c4i = lane & 3;
    #pragma unroll
    for (int t = 0; t < 4; t++) {
        int r0 = m0 + wm + t * 16 + g4;
        #pragma unroll
        for (int u = 0; u < 4; u++) {
            int col = n0 + wn + u * 8 + c4i * 2;
            *(float2*)&C[(size_t)r0 * N + col] = make_float2(acc[t][u][0], acc[t][u][1]);
            *(float2*)&C[(size_t)(r0 + 8) * N + col] = make_float2(acc[t][u][2], acc[t][u][3]);
        }
    }
}

// ---------------- G = C @ B^T per (chunk, group) ----------------------------
#define GALD 72
__global__ __launch_bounds__(256)
void gemmG_kernel() {
    __shared__ __align__(16) __half sC[128 * GALD];
    __shared__ __align__(16) __half sB[128 * GALD];
    int k = blockIdx.x, g = blockIdx.y;
    int tid = threadIdx.x, lane = tid & 31, wid = tid >> 5;
    int lb = k * CHUNKSZ;

    #pragma unroll
    for (int it = 0; it < 8; it++) {
        int q = tid + it * 256;
        int which = q >> 10, rem = q & 1023;
        int r = rem >> 3, c8 = (rem & 7) * 8;
        const __half* src = (which ? g_Bh : g_Ch) + ((size_t)(lb + r) * NG + g) * DS + c8;
        __half* dst = (which ? sB : sC) + r * GALD + c8;
        *(uint4*)dst = *(const uint4*)src;
    }
    __syncthreads();

    uint32_t sCb = s2u(sC), sBb = s2u(sB);
    int wm = (wid & 1) * 64, wn = (wid >> 1) * 32;
    int lr = lane & 7;
    int a_row = lr + ((lane >> 3) & 1) * 8;
    int a_col = ((lane >> 4) & 1) * 8;
    uint32_t aoff[4];
    #pragma unroll
    for (int t = 0; t < 4; t++)
        aoff[t] = sCb + (uint32_t)(((wm + t * 16 + a_row) * GALD + a_col) * 2);
    int b_row = lr + ((lane >> 4) & 1) * 8;
    int b_col = ((lane >> 3) & 1) * 8;
    uint32_t boff[2];
    #pragma unroll
    for (int v = 0; v < 2; v++)
        boff[v] = sBb + (uint32_t)(((wn + v * 16 + b_row) * GALD + b_col) * 2);

    float acc[4][4][4];
    #pragma unroll
    for (int t = 0; t < 4; t++)
        #pragma unroll
        for (int u = 0; u < 4; u++)
            #pragma unroll
            for (int v = 0; v < 4; v++) acc[t][u][v] = 0.f;

    #pragma unroll
    for (int ks = 0; ks < 4; ks++) {
        uint32_t kadd = ks * 32;
        uint32_t af[4][4];
        #pragma unroll
        for (int t = 0; t < 4; t++) ldsm4(af[t], aoff[t] + kadd);
        uint32_t bf[2][4];
        #pragma unroll
        for (int v = 0; v < 2; v++) ldsm4(bf[v], boff[v] + kadd);
        #pragma unroll
        for (int u = 0; u < 4; u++) {
            uint32_t b0 = bf[u >> 1][(u & 1) * 2 + 0];
            uint32_t b1 = bf[u >> 1][(u & 1) * 2 + 1];
            #pragma unroll
            for (int t = 0; t < 4; t++) mma16n8k16(acc[t][u], af[t], b0, b1);
        }
    }

    __half* Gout = g_G + ((size_t)(k * NG + g) << 14);
    int g4 = lane >> 2, c4i = lane & 3;
    #pragma unroll
    for (int t = 0; t < 4; t++) {
        int r0 = wm + t * 16 + g4;
        #pragma unroll
        for (int u = 0; u < 4; u++) {
            int col = wn + u * 8 + c4i * 2;
            *(uint32_t*)&Gout[r0 * 128 + col] = pack_h2(acc[t][u][0], acc[t][u][1]);
            *(uint32_t*)&Gout[(r0 + 8) * 128 + col] = pack_h2(acc[t][u][2], acc[t][u][3]);
        }
    }
}

// ---------------- per-chunk end states: S[k,h,p,n] --------------------------
__global__ void states_kernel(const float* __restrict__ Bin) {
    int k = blockIdx.x, h = blockIdx.y;
    int tid = threadIdx.x;
    int p = tid & 63, quad = tid >> 6;
    float a = g_a[h], dtv = g_dt[h];
    int g = h / HPG;
    __shared__ float sx[8 * 64], sbuf[8 * 64];
    float acc[16];
    #pragma unroll
    for (int m = 0; m < 16; m++) acc[m] = 0.f;
    int lb = k * CHUNKSZ;
    for (int jb = 0; jb < CHUNKSZ; jb += 8) {
        __syncthreads();
        #pragma unroll
        for (int it = 0; it < 2; it++) {
            int e = tid + it * 256;
            int jj = e >> 6, pp = e & 63;
            int l = lb + jb + jj;
            sx[e] = g_xz[(size_t)l * IN2 + h * HD + pp];
            sbuf[e] = Bin[((size_t)l * NG + g) * DS + pp];
        }
        __syncthreads();
        #pragma unroll
        for (int jj = 0; jj < 8; jj++) {
            int j = jb + jj;
            float dec = expf(a * (float)(CHUNKSZ - 1 - j)) * dtv;
            float v = sx[jj * 64 + p] * dec;
            #pragma unroll
            for (int m = 0; m < 16; m++)
                acc[m] += v * sbuf[jj * 64 + quad + 4 * m];
        }
    }
    size_t base = ((size_t)(k * NH + h)) << 12;
    #pragma unroll
    for (int m = 0; m < 16; m++)
        g_states[base + p * 64 + quad + 4 * m] = acc[m];
}

// ---------------- inter-chunk scan (fp16 prev out, [p][n]) ------------------
__global__ void scan_kernel() {
    int h = blockIdx.x;
    float cd = expf(g_a[h] * (float)CHUNKSZ);
    for (int e = threadIdx.x; e < HD * DS; e += 256) {
        float carry = 0.f;
        #pragma unroll
        for (int k = 0; k < NCHUNK; k++) {
            size_t base = ((size_t)(k * NH + h)) << 12;
            g_prevh[base + e] = __float2half(carry);
            carry = carry * cd + g_states[base + e];
        }
    }
}

// ---------------- yblock: Y = [G' | C*exp] @ [X^T | prev]^T via mma ---------
#define KTOT 192
#define ALD2 200
#define YB_SMEM ((128 * ALD2 + 64 * ALD2) * 2 + 132 * 4)

__global__ __launch_bounds__(256, 2)
void yblock_mma(const float* __restrict__ Cin, const float* __restrict__ Dv) {
    extern __shared__ __align__(16) char sraw[];
    __half* sA  = (__half*)sraw;               // [128][ALD2]
    __half* sBt = sA + 128 * ALD2;             // [64][ALD2]
    float* sDec = (float*)(sBt + 64 * ALD2);   // [132]

    int k = blockIdx.x, h = blockIdx.y;
    int tid = threadIdx.x, lane = tid & 31, wid = tid >> 5;
    float a = g_a[h], dtv = g_dt[h], Dh = Dv[h];
    int g = h / HPG;
    int lb = k * CHUNKSZ;

    for (int d = tid; d < 130; d += 256) sDec[d] = expf(a * (float)d);
    __syncthreads();

    // A cols 0..127: masked & decayed G
    {
        const __half* Gh = g_G + ((size_t)(k * NG + g) << 14);
        for (int q = tid; q < 128 * 64; q += 256) {
            int i = q >> 6, j2 = (q & 63) * 2;
            __half2 gv = *(const __half2*)&Gh[i * 128 + j2];
            float2 f = __half22float2(gv);
            float w0 = (j2 <= i) ? f.x * dtv * sDec[i - j2] : 0.f;
            float w1 = (j2 + 1 <= i) ? f.y * dtv * sDec[i - j2 - 1] : 0.f;
            *(uint32_t*)&sA[i * ALD2 + j2] = pack_h2(w0, w1);
        }
    }
    // A cols 128..191: C * exp((i+1)a)
    for (int q = tid; q < 128 * 16; q += 256) {
        int i = q >> 4, n4 = (q & 15) * 4;
        float4 c = *(const float4*)&Cin[((size_t)(lb + i) * NG + g) * DS + n4];
        float sc = sDec[i + 1];
        uint2 o;
        o.x = pack_h2(c.x * sc, c.y * sc);
        o.y = pack_h2(c.z * sc, c.w * sc);
        *(uint2*)&sA[i * ALD2 + 128 + n4] = o;
    }
    // B cols 0..127: X^T (x[j,p] -> sBt[p][j]), fp32 -> fp16
    for (int q = tid; q < 64 * 16; q += 256) {
        int j = (q >> 4) * 2, p4 = (q & 15) * 4;
        const float* x0 = &g_xz[(size_t)(lb + j) * IN2 + h * HD + p4];
        const float* x1 = x0 + IN2;
        float4 v0 = *(const float4*)x0;
        float4 v1 = *(const float4*)x1;
        *(uint32_t*)&sBt[(p4 + 0) * ALD2 + j] = pack_h2(v0.x, v1.x);
        *(uint32_t*)&sBt[(p4 + 1) * ALD2 + j] = pack_h2(v0.y, v1.y);
        *(uint32_t*)&sBt[(p4 + 2) * ALD2 + j] = pack_h2(v0.z, v1.z);
        *(uint32_t*)&sBt[(p4 + 3) * ALD2 + j] = pack_h2(v0.w, v1.w);
    }
    // B cols 128..191: prev fp16 [p][n]
    {
        const uint4* Pv = (const uint4*)(g_prevh + ((size_t)(k * NH + h) << 12));
        for (int q = tid; q < 512; q += 256) {
            int p = q >> 3, c8 = (q & 7) * 8;
            *(uint4*)&sBt[p * ALD2 + 128 + c8] = Pv[q];
        }
    }
    __syncthreads();

    uint32_t sAb = s2u(sA), sBb = s2u(sBt);
    int wm = (wid & 1) * 64, wn = (wid >> 1) * 16;
    int lr = lane & 7;
    int a_row = lr + ((lane >> 3) & 1) * 8;
    int a_col = ((lane >> 4) & 1) * 8;
    uint32_t aoff[4];
    #pragma unroll
    for (int t = 0; t < 4; t++)
        aoff[t] = sAb + (uint32_t)(((wm + t * 16 + a_row) * ALD2 + a_col) * 2);
    int b_row = lr + ((lane >> 4) & 1) * 8;
    int b_col = ((lane >> 3) & 1) * 8;
    uint32_t boff = sBb + (uint32_t)(((wn + b_row) * ALD2 + b_col) * 2);

    float acc[4][2][4];
    #pragma unroll
    for (int t = 0; t < 4; t++)
        #pragma unroll
        for (int u = 0; u < 2; u++)
            #pragma unroll
            for (int v = 0; v < 4; v++) acc[t][u][v] = 0.f;

    #pragma unroll
    for (int ks = 0; ks < KTOT / 16; ks++) {
        uint32_t kadd = ks * 32;
        uint32_t af[4][4];
        #pragma unroll
        for (int t = 0; t < 4; t++) ldsm4(af[t], aoff[t] + kadd);
        uint32_t bf[4];
        ldsm4(bf, boff + kadd);
        #pragma unroll
        for (int u = 0; u < 2; u++) {
            uint32_t b0 = bf[u * 2 + 0];
            uint32_t b1 = bf[u * 2 + 1];
            #pragma unroll
            for (int t = 0; t < 4; t++) mma16n8k16(acc[t][u], af[t], b0, b1);
        }
    }

    int g4 = lane >> 2, c4i = lane & 3;
    #pragma unroll
    for (int t = 0; t < 4; t++) {
        #pragma unroll
        for (int half_ = 0; half_ < 2; half_++) {
            int i = wm + t * 16 + g4 + half_ * 8;
            int l = lb + i;
            #pragma unroll
            for (int u = 0; u < 2; u++) {
                int p = wn + u * 8 + c4i * 2;
                float y0 = acc[t][u][half_ * 2 + 0];
                float y1 = acc[t][u][half_ * 2 + 1];
                float x0 = __half2float(sBt[p * ALD2 + i]);
                float x1 = __half2float(sBt[(p + 1) * ALD2 + i]);
                float2 zv = *(const float2*)&g_xz[(size_t)l * IN2 + INNER + h * HD + p];
                y0 = (y0 + x0 * Dh) / (1.f + expf(-zv.x));
                y1 = (y1 + x1 * Dh) / (1.f + expf(-zv.y));
                *(uint32_t*)&g_ygh[(size_t)l * INNER + h * HD + p] = pack_h2(y0, y1);
            }
        }
    }
}

// ---------------- launcher --------------------------------------------------
extern "C" void kernel_launch(void* const* d_in, const int* in_sizes, int n_in,
                              void* d_out, int out_size) {
    (void)in_sizes; (void)n_in; (void)out_size;
    const float* hidden = (const float*)d_in[0];
    const float* W_in   = (const float*)d_in[1];
    const float* W_out  = (const float*)d_in[2];
    const float* A_log  = (const float*)d_in[3];
    const float* Dv     = (const float*)d_in[4];
    const float* dtb    = (const float*)d_in[5];
    const float* Bin    = (const float*)d_in[6];
    const float* Cin    = (const float*)d_in[7];
    float* out = (float*)d_out;

    float *xz_ptr;
    __half *ygh_ptr, *hidh_ptr, *w1h_ptr, *w2h_ptr, *bh_ptr, *ch_ptr;
    cudaGetSymbolAddress((void**)&xz_ptr, g_xz);
    cudaGetSymbolAddress((void**)&ygh_ptr, g_ygh);
    cudaGetSymbolAddress((void**)&hidh_ptr, g_hidh);
    cudaGetSymbolAddress((void**)&w1h_ptr, g_w1h);
    cudaGetSymbolAddress((void**)&w2h_ptr, g_w2h);
    cudaGetSymbolAddress((void**)&bh_ptr, g_Bh);
    cudaGetSymbolAddress((void**)&ch_ptr, g_Ch);

    cudaFuncSetAttribute(gemm_mma, cudaFuncAttributeMaxDynamicSharedMemorySize, GM_SMEM);
    cudaFuncSetAttribute(yblock_mma, cudaFuncAttributeMaxDynamicSharedMemorySize, YB_SMEM);

    // launch order: gemm1 is 4th (ncu captures it)
    hparams_kernel<<<1, 128>>>(A_log, dtb);                                   // 1
    to_half_kernel<<<1184, 256>>>(W_in,   w1h_ptr,  (IN2 * DMODEL) / 8);      // 2
    to_half_kernel<<<1184, 256>>>(hidden, hidh_ptr, (L_TOK * DMODEL) / 8);    // 3

    // GEMM1: xz[L, IN2] = hid @ W_in^T
    {
        int tiles_m = L_TOK / 128;
        int tiles_n = IN2 / 256;
        gemm_mma<<<tiles_m * tiles_n, 512, GM_SMEM>>>(hidh_ptr, w1h_ptr, xz_ptr,
                                                      L_TOK, IN2, DMODEL, tiles_m);  // 4
    }

    to_half_kernel<<<256, 256>>>(Bin, bh_ptr, (L_TOK * NG * DS) / 8);         // 5
    to_half_kernel<<<256, 256>>>(Cin, ch_ptr, (L_TOK * NG * DS) / 8);         // 6
    gemmG_kernel<<<dim3(NCHUNK, NG), 256>>>();                                // 7
    states_kernel<<<dim3(NCHUNK, NH), 256>>>(Bin);                            // 8
    scan_kernel<<<NH, 256>>>();                                               // 9
    yblock_mma<<<dim3(NCHUNK, NH), 256, YB_SMEM>>>(Cin, Dv);                  // 10

    to_half_kernel<<<1184, 256>>>(W_out, w2h_ptr, (DMODEL * INNER) / 8);      // 11

    // GEMM2: out = yg @ W_out^T
    {
        int tiles_m = L_TOK / 128;
        int tiles_n = DMODEL / 256;
        gemm_mma<<<tiles_m * tiles_n, 512, GM_SMEM>>>(ygh_ptr, w2h_ptr, out,
                                                      L_TOK, DMODEL, INNER, tiles_m); // 12
    }
}

// round 16
// speedup vs baseline: 1.0615x; 1.0615x over previous
#include <cuda_runtime.h>
#include <cuda_fp16.h>
#include <math.h>
#include <stdint.h>

// ---------------- problem constants ----------------
#define L_TOK   4096
#define DMODEL  3584
#define NH      112
#define HD      64
#define DS      64
#define CHUNKSZ 128
#define NCHUNK  32
#define NG      2
#define HPG     (NH / NG)          // 56
#define INNER   (NH * HD)          // 7168
#define IN2     (2 * INNER)        // 14336

// ---------------- scratch (device globals; no cudaMalloc allowed) ----------
__device__ float  g_xz[(size_t)L_TOK * IN2];           // [x | z]  (fp32)
__device__ __half g_ygh[(size_t)L_TOK * INNER];        // gated y  (fp16)
__device__ float  g_states[(size_t)NCHUNK * NH * HD * DS];  // [k][h][p][n]
__device__ __align__(16) __half g_prevh[(size_t)NCHUNK * NH * HD * DS]; // fp16 [p][n]
__device__ __align__(16) __half g_G[(size_t)NCHUNK * NG * CHUNKSZ * CHUNKSZ];
__device__ __half g_hidh[(size_t)L_TOK * DMODEL];
__device__ __half g_w1h[(size_t)IN2 * DMODEL];
__device__ __half g_w2h[(size_t)DMODEL * INNER];
__device__ float  g_dt[NH];
__device__ float  g_a[NH];

// ---------------- helpers ---------------------------------------------------
__device__ __forceinline__ uint32_t s2u(const void* p) {
    uint32_t a;
    asm("{ .reg .u64 t; cvta.to.shared.u64 t, %1; cvt.u32.u64 %0, t; }"
        : "=r"(a) : "l"(p));
    return a;
}
__device__ __forceinline__ void cpasync16(uint32_t saddr, const void* g) {
    asm volatile("cp.async.cg.shared.global [%0], [%1], 16;" :: "r"(saddr), "l"(g));
}
__device__ __forceinline__ void ldsm4(uint32_t* r, uint32_t addr) {
    asm volatile("ldmatrix.sync.aligned.m8n8.x4.shared.b16 {%0,%1,%2,%3}, [%4];"
                 : "=r"(r[0]), "=r"(r[1]), "=r"(r[2]), "=r"(r[3]) : "r"(addr));
}
__device__ __forceinline__ void mma16n8k16(float* d, const uint32_t* a,
                                           uint32_t b0, uint32_t b1) {
    asm volatile(
        "mma.sync.aligned.m16n8k16.row.col.f32.f16.f16.f32 "
        "{%0,%1,%2,%3}, {%4,%5,%6,%7}, {%8,%9}, {%0,%1,%2,%3};"
        : "+f"(d[0]), "+f"(d[1]), "+f"(d[2]), "+f"(d[3])
        : "r"(a[0]), "r"(a[1]), "r"(a[2]), "r"(a[3]), "r"(b0), "r"(b1));
}
__device__ __forceinline__ uint32_t pack_h2(float lo, float hi) {
    uint32_t r;
    asm("cvt.rn.f16x2.f32 %0, %1, %2;" : "=r"(r) : "f"(hi), "f"(lo));
    return r;
}

// ---------------- per-head parameters --------------------------------------
__global__ void hparams_kernel(const float* __restrict__ A_log,
                               const float* __restrict__ dt_bias) {
    int h = threadIdx.x;
    if (h < NH) {
        float xv = 0.1f + dt_bias[h];
        float sp = (xv > 20.f) ? xv : log1pf(expf(xv));
        g_dt[h] = sp;
        g_a[h]  = -expf(A_log[h]) * sp;
    }
}

// ---------------- fp32 -> fp16 conversion ----------------------------------
__global__ void to_half_kernel(const float* __restrict__ in, __half* __restrict__ out, int n8) {
    int i = blockIdx.x * blockDim.x + threadIdx.x;
    int stride = gridDim.x * blockDim.x;
    for (; i < n8; i += stride) {
        float4 a = ((const float4*)in)[2 * i];
        float4 b = ((const float4*)in)[2 * i + 1];
        uint4 o;
        o.x = pack_h2(a.x, a.y);
        o.y = pack_h2(a.z, a.w);
        o.z = pack_h2(b.x, b.y);
        o.w = pack_h2(b.z, b.w);
        ((uint4*)out)[i] = o;
    }
}

// ---------------- FP16 GEMM (R10 proven): 128x256x64, 512 thr, 4-stage -----
#define KTH      64
#define ALDH     72
#define A_H      (128 * ALDH)
#define B_H      (256 * ALDH)
#define STGB     ((A_H + B_H) * 2)           // 55296 B
#define NSTG     4
#define GM_SMEM  (NSTG * STGB)               // 221184 B

__global__ __launch_bounds__(512, 1)
void gemm_mma(const __half* __restrict__ A, const __half* __restrict__ B,
              float* __restrict__ C, int M, int N, int K, int tiles_m) {
    extern __shared__ __align__(16) char smraw[];
    uint32_t sbase = s2u(smraw);

    int tid = threadIdx.x, lane = tid & 31, wid = tid >> 5;
    int wm = (wid & 1) * 64;
    int wn = (wid >> 1) * 32;
    int bid = blockIdx.x;
    int m0 = (bid % tiles_m) * 128;
    int n0 = (bid / tiles_m) * 256;

    const __half* gA[2]; uint32_t oA[2];
    #pragma unroll
    for (int it = 0; it < 2; it++) {
        int q = tid + it * 512;
        int r = q >> 3, c8 = (q & 7) * 8;
        gA[it] = A + (size_t)(m0 + r) * K + c8;
        oA[it] = (uint32_t)(r * ALDH + c8) * 2;
    }
    const __half* gB[4]; uint32_t oB[4];
    #pragma unroll
    for (int it = 0; it < 4; it++) {
        int q = tid + it * 512;
        int r = q >> 3, c8 = (q & 7) * 8;
        gB[it] = B + (size_t)(n0 + r) * K + c8;
        oB[it] = (uint32_t)(A_H + r * ALDH + c8) * 2;
    }

    int lr = lane & 7;
    int a_row = lr + ((lane >> 3) & 1) * 8;
    int a_col = ((lane >> 4) & 1) * 8;
    uint32_t aoff[4];
    #pragma unroll
    for (int t = 0; t < 4; t++)
        aoff[t] = sbase + (uint32_t)(((wm + t * 16 + a_row) * ALDH + a_col) * 2);
    int b_row = lr + ((lane >> 4) & 1) * 8;
    int b_col = ((lane >> 3) & 1) * 8;
    uint32_t boff[2];
    #pragma unroll
    for (int v = 0; v < 2; v++)
        boff[v] = sbase + (uint32_t)((A_H + (wn + v * 16 + b_row) * ALDH + b_col) * 2);

    const int NKC = K / KTH;

    #pragma unroll
    for (int s = 0; s < NSTG - 1; s++) {
        uint32_t sb = sbase + s * STGB;
        #pragma unroll
        for (int it = 0; it < 2; it++) cpasync16(sb + oA[it], gA[it] + s * KTH);
        #pragma unroll
        for (int it = 0; it < 4; it++) cpasync16(sb + oB[it], gB[it] + s * KTH);
        asm volatile("cp.async.commit_group;");
    }

    float acc[4][4][4];
    #pragma unroll
    for (int t = 0; t < 4; t++)
        #pragma unroll
        for (int u = 0; u < 4; u++)
            #pragma unroll
            for (int v = 0; v < 4; v++) acc[t][u][v] = 0.f;

    for (int kb = 0; kb < NKC; kb++) {
        int st = kb & (NSTG - 1);
        asm volatile("cp.async.wait_group %0;" :: "n"(NSTG - 2));
        __syncthreads();
        {
            int fc = kb + NSTG - 1;
            if (fc < NKC) {
                uint32_t sb = sbase + (fc & (NSTG - 1)) * STGB;
                #pragma unroll
                for (int it = 0; it < 2; it++) cpasync16(sb + oA[it], gA[it] + fc * KTH);
                #pragma unroll
                for (int it = 0; it < 4; it++) cpasync16(sb + oB[it], gB[it] + fc * KTH);
            }
            asm volatile("cp.async.commit_group;");
        }
        uint32_t stb = st * STGB;
        #pragma unroll
        for (int ks = 0; ks < 4; ks++) {
            uint32_t kadd = stb + ks * 32;
            uint32_t af[4][4];
            #pragma unroll
            for (int t = 0; t < 4; t++) ldsm4(af[t], aoff[t] + kadd);
            uint32_t bf[2][4];
            #pragma unroll
            for (int v = 0; v < 2; v++) ldsm4(bf[v], boff[v] + kadd);
            #pragma unroll
            for (int u = 0; u < 4; u++) {
                uint32_t b0 = bf[u >> 1][(u & 1) * 2 + 0];
                uint32_t b1 = bf[u >> 1][(u & 1) * 2 + 1];
                #pragma unroll
                for (int t = 0; t < 4; t++) mma16n8k16(acc[t][u], af[t], b0, b1);
            }
        }
    }

    int g4 = lane >> 2, c4i = lane & 3;
    #pragma unroll
    for (int t = 0; t < 4; t++) {
        int r0 = m0 + wm + t * 16 + g4;
        #pragma unroll
        for (int u = 0; u < 4; u++) {
            int col = n0 + wn + u * 8 + c4i * 2;
            *(float2*)&C[(size_t)r0 * N + col] = make_float2(acc[t][u][0], acc[t][u][1]);
            *(float2*)&C[(size_t)(r0 + 8) * N + col] = make_float2(acc[t][u][2], acc[t][u][3]);
        }
    }
}

// ---------------- G = C @ B^T per (chunk, group), fp32 in, convert in-kernel
#define GALD 72
__global__ __launch_bounds__(256)
void gemmG_kernel(const float* __restrict__ Bin, const float* __restrict__ Cin) {
    __shared__ __align__(16) __half sC[128 * GALD];
    __shared__ __align__(16) __half sB[128 * GALD];
    int k = blockIdx.x, g = blockIdx.y;
    int tid = threadIdx.x, lane = tid & 31, wid = tid >> 5;
    int lb = k * CHUNKSZ;

    // load fp32 B/C and convert to fp16 smem tiles:
    // 2 tiles x 128 rows x 64 cols = 2 x 2048 float4 (8 cols each)
    #pragma unroll
    for (int it = 0; it < 8; it++) {
        int q = tid + it * 256;
        int which = q >> 10, rem = q & 1023;
        int r = rem >> 3, c8 = (rem & 7) * 8;
        const float* src = (which ? Bin : Cin) + ((size_t)(lb + r) * NG + g) * DS + c8;
        float4 v0 = *(const float4*)src;
        float4 v1 = *(const float4*)(src + 4);
        uint4 o;
        o.x = pack_h2(v0.x, v0.y);
        o.y = pack_h2(v0.z, v0.w);
        o.z = pack_h2(v1.x, v1.y);
        o.w = pack_h2(v1.z, v1.w);
        __half* dst = (which ? sB : sC) + r * GALD + c8;
        *(uint4*)dst = o;
    }
    __syncthreads();

    uint32_t sCb = s2u(sC), sBb = s2u(sB);
    int wm = (wid & 1) * 64, wn = (wid >> 1) * 32;
    int lr = lane & 7;
    int a_row = lr + ((lane >> 3) & 1) * 8;
    int a_col = ((lane >> 4) & 1) * 8;
    uint32_t aoff[4];
    #pragma unroll
    for (int t = 0; t < 4; t++)
        aoff[t] = sCb + (uint32_t)(((wm + t * 16 + a_row) * GALD + a_col) * 2);
    int b_row = lr + ((lane >> 4) & 1) * 8;
    int b_col = ((lane >> 3) & 1) * 8;
    uint32_t boff[2];
    #pragma unroll
    for (int v = 0; v < 2; v++)
        boff[v] = sBb + (uint32_t)(((wn + v * 16 + b_row) * GALD + b_col) * 2);

    float acc[4][4][4];
    #pragma unroll
    for (int t = 0; t < 4; t++)
        #pragma unroll
        for (int u = 0; u < 4; u++)
            #pragma unroll
            for (int v = 0; v < 4; v++) acc[t][u][v] = 0.f;

    #pragma unroll
    for (int ks = 0; ks < 4; ks++) {
        uint32_t kadd = ks * 32;
        uint32_t af[4][4];
        #pragma unroll
        for (int t = 0; t < 4; t++) ldsm4(af[t], aoff[t] + kadd);
        uint32_t bf[2][4];
        #pragma unroll
        for (int v = 0; v < 2; v++) ldsm4(bf[v], boff[v] + kadd);
        #pragma unroll
        for (int u = 0; u < 4; u++) {
            uint32_t b0 = bf[u >> 1][(u & 1) * 2 + 0];
            uint32_t b1 = bf[u >> 1][(u & 1) * 2 + 1];
            #pragma unroll
            for (int t = 0; t < 4; t++) mma16n8k16(acc[t][u], af[t], b0, b1);
        }
    }

    __half* Gout = g_G + ((size_t)(k * NG + g) << 14);
    int g4 = lane >> 2, c4i = lane & 3;
    #pragma unroll
    for (int t = 0; t < 4; t++) {
        int r0 = wm + t * 16 + g4;
        #pragma unroll
        for (int u = 0; u < 4; u++) {
            int col = wn + u * 8 + c4i * 2;
            *(uint32_t*)&Gout[r0 * 128 + col] = pack_h2(acc[t][u][0], acc[t][u][1]);
            *(uint32_t*)&Gout[(r0 + 8) * 128 + col] = pack_h2(acc[t][u][2], acc[t][u][3]);
        }
    }
}

// ---------------- per-chunk end states: S[k,h,p,n] --------------------------
__global__ void states_kernel(const float* __restrict__ Bin) {
    int k = blockIdx.x, h = blockIdx.y;
    int tid = threadIdx.x;
    int p = tid & 63, quad = tid >> 6;
    float a = g_a[h], dtv = g_dt[h];
    int g = h / HPG;
    __shared__ float sx[8 * 64], sbuf[8 * 64];
    float acc[16];
    #pragma unroll
    for (int m = 0; m < 16; m++) acc[m] = 0.f;
    int lb = k * CHUNKSZ;
    for (int jb = 0; jb < CHUNKSZ; jb += 8) {
        __syncthreads();
        #pragma unroll
        for (int it = 0; it < 2; it++) {
            int e = tid + it * 256;
            int jj = e >> 6, pp = e & 63;
            int l = lb + jb + jj;
            sx[e] = g_xz[(size_t)l * IN2 + h * HD + pp];
            sbuf[e] = Bin[((size_t)l * NG + g) * DS + pp];
        }
        __syncthreads();
        #pragma unroll
        for (int jj = 0; jj < 8; jj++) {
            int j = jb + jj;
            float dec = expf(a * (float)(CHUNKSZ - 1 - j)) * dtv;
            float v = sx[jj * 64 + p] * dec;
            #pragma unroll
            for (int m = 0; m < 16; m++)
                acc[m] += v * sbuf[jj * 64 + quad + 4 * m];
        }
    }
    size_t base = ((size_t)(k * NH + h)) << 12;
    #pragma unroll
    for (int m = 0; m < 16; m++)
        g_states[base + p * 64 + quad + 4 * m] = acc[m];
}

// ---------------- inter-chunk scan (fp16 prev out, [p][n]) ------------------
__global__ void scan_kernel() {
    int h = blockIdx.x;
    float cd = expf(g_a[h] * (float)CHUNKSZ);
    for (int e = threadIdx.x; e < HD * DS; e += 256) {
        float carry = 0.f;
        #pragma unroll
        for (int k = 0; k < NCHUNK; k++) {
            size_t base = ((size_t)(k * NH + h)) << 12;
            g_prevh[base + e] = __float2half(carry);
            carry = carry * cd + g_states[base + e];
        }
    }
}

// ---------------- yblock: Y = [G' | C*exp] @ [X^T | prev]^T via mma ---------
#define KTOT 192
#define ALD2 200
#define YB_SMEM ((128 * ALD2 + 64 * ALD2) * 2 + 132 * 4)

__global__ __launch_bounds__(256, 2)
void yblock_mma(const float* __restrict__ Cin, const float* __restrict__ Dv) {
    extern __shared__ __align__(16) char sraw[];
    __half* sA  = (__half*)sraw;               // [128][ALD2]
    __half* sBt = sA + 128 * ALD2;             // [64][ALD2]
    float* sDec = (float*)(sBt + 64 * ALD2);   // [132]

    int k = blockIdx.x, h = blockIdx.y;
    int tid = threadIdx.x, lane = tid & 31, wid = tid >> 5;
    float a = g_a[h], dtv = g_dt[h], Dh = Dv[h];
    int g = h / HPG;
    int lb = k * CHUNKSZ;

    for (int d = tid; d < 130; d += 256) sDec[d] = expf(a * (float)d);
    __syncthreads();

    // A cols 0..127: masked & decayed G
    {
        const __half* Gh = g_G + ((size_t)(k * NG + g) << 14);
        for (int q = tid; q < 128 * 64; q += 256) {
            int i = q >> 6, j2 = (q & 63) * 2;
            __half2 gv = *(const __half2*)&Gh[i * 128 + j2];
            float2 f = __half22float2(gv);
            float w0 = (j2 <= i) ? f.x * dtv * sDec[i - j2] : 0.f;
            float w1 = (j2 + 1 <= i) ? f.y * dtv * sDec[i - j2 - 1] : 0.f;
            *(uint32_t*)&sA[i * ALD2 + j2] = pack_h2(w0, w1);
        }
    }
    // A cols 128..191: C * exp((i+1)a)
    for (int q = tid; q < 128 * 16; q += 256) {
        int i = q >> 4, n4 = (q & 15) * 4;
        float4 c = *(const float4*)&Cin[((size_t)(lb + i) * NG + g) * DS + n4];
        float sc = sDec[i + 1];
        uint2 o;
        o.x = pack_h2(c.x * sc, c.y * sc);
        o.y = pack_h2(c.z * sc, c.w * sc);
        *(uint2*)&sA[i * ALD2 + 128 + n4] = o;
    }
    // B cols 0..127: X^T (x[j,p] -> sBt[p][j]), fp32 -> fp16
    for (int q = tid; q < 64 * 16; q += 256) {
        int j = (q >> 4) * 2, p4 = (q & 15) * 4;
        const float* x0 = &g_xz[(size_t)(lb + j) * IN2 + h * HD + p4];
        const float* x1 = x0 + IN2;
        float4 v0 = *(const float4*)x0;
        float4 v1 = *(const float4*)x1;
        *(uint32_t*)&sBt[(p4 + 0) * ALD2 + j] = pack_h2(v0.x, v1.x);
        *(uint32_t*)&sBt[(p4 + 1) * ALD2 + j] = pack_h2(v0.y, v1.y);
        *(uint32_t*)&sBt[(p4 + 2) * ALD2 + j] = pack_h2(v0.z, v1.z);
        *(uint32_t*)&sBt[(p4 + 3) * ALD2 + j] = pack_h2(v0.w, v1.w);
    }
    // B cols 128..191: prev fp16 [p][n]
    {
        const uint4* Pv = (const uint4*)(g_prevh + ((size_t)(k * NH + h) << 12));
        for (int q = tid; q < 512; q += 256) {
            int p = q >> 3, c8 = (q & 7) * 8;
            *(uint4*)&sBt[p * ALD2 + 128 + c8] = Pv[q];
        }
    }
    __syncthreads();

    uint32_t sAb = s2u(sA), sBb = s2u(sBt);
    int wm = (wid & 1) * 64, wn = (wid >> 1) * 16;
    int lr = lane & 7;
    int a_row = lr + ((lane >> 3) & 1) * 8;
    int a_col = ((lane >> 4) & 1) * 8;
    uint32_t aoff[4];
    #pragma unroll
    for (int t = 0; t < 4; t++)
        aoff[t] = sAb + (uint32_t)(((wm + t * 16 + a_row) * ALD2 + a_col) * 2);
    int b_row = lr + ((lane >> 4) & 1) * 8;
    int b_col = ((lane >> 3) & 1) * 8;
    uint32_t boff = sBb + (uint32_t)(((wn + b_row) * ALD2 + b_col) * 2);

    float acc[4][2][4];
    #pragma unroll
    for (int t = 0; t < 4; t++)
        #pragma unroll
        for (int u = 0; u < 2; u++)
            #pragma unroll
            for (int v = 0; v < 4; v++) acc[t][u][v] = 0.f;

    #pragma unroll
    for (int ks = 0; ks < KTOT / 16; ks++) {
        uint32_t kadd = ks * 32;
        uint32_t af[4][4];
        #pragma unroll
        for (int t = 0; t < 4; t++) ldsm4(af[t], aoff[t] + kadd);
        uint32_t bf[4];
        ldsm4(bf, boff + kadd);
        #pragma unroll
        for (int u = 0; u < 2; u++) {
            uint32_t b0 = bf[u * 2 + 0];
            uint32_t b1 = bf[u * 2 + 1];
            #pragma unroll
            for (int t = 0; t < 4; t++) mma16n8k16(acc[t][u], af[t], b0, b1);
        }
    }

    int g4 = lane >> 2, c4i = lane & 3;
    #pragma unroll
    for (int t = 0; t < 4; t++) {
        #pragma unroll
        for (int half_ = 0; half_ < 2; half_++) {
            int i = wm + t * 16 + g4 + half_ * 8;
            int l = lb + i;
            #pragma unroll
            for (int u = 0; u < 2; u++) {
                int p = wn + u * 8 + c4i * 2;
                float y0 = acc[t][u][half_ * 2 + 0];
                float y1 = acc[t][u][half_ * 2 + 1];
                float x0 = __half2float(sBt[p * ALD2 + i]);
                float x1 = __half2float(sBt[(p + 1) * ALD2 + i]);
                float2 zv = *(const float2*)&g_xz[(size_t)l * IN2 + INNER + h * HD + p];
                y0 = (y0 + x0 * Dh) / (1.f + expf(-zv.x));
                y1 = (y1 + x1 * Dh) / (1.f + expf(-zv.y));
                *(uint32_t*)&g_ygh[(size_t)l * INNER + h * HD + p] = pack_h2(y0, y1);
            }
        }
    }
}

// ---------------- launcher --------------------------------------------------
extern "C" void kernel_launch(void* const* d_in, const int* in_sizes, int n_in,
                              void* d_out, int out_size) {
    (void)in_sizes; (void)n_in; (void)out_size;
    const float* hidden = (const float*)d_in[0];
    const float* W_in   = (const float*)d_in[1];
    const float* W_out  = (const float*)d_in[2];
    const float* A_log  = (const float*)d_in[3];
    const float* Dv     = (const float*)d_in[4];
    const float* dtb    = (const float*)d_in[5];
    const float* Bin    = (const float*)d_in[6];
    const float* Cin    = (const float*)d_in[7];
    float* out = (float*)d_out;

    float *xz_ptr;
    __half *ygh_ptr, *hidh_ptr, *w1h_ptr, *w2h_ptr;
    cudaGetSymbolAddress((void**)&xz_ptr, g_xz);
    cudaGetSymbolAddress((void**)&ygh_ptr, g_ygh);
    cudaGetSymbolAddress((void**)&hidh_ptr, g_hidh);
    cudaGetSymbolAddress((void**)&w1h_ptr, g_w1h);
    cudaGetSymbolAddress((void**)&w2h_ptr, g_w2h);

    cudaFuncSetAttribute(gemm_mma, cudaFuncAttributeMaxDynamicSharedMemorySize, GM_SMEM);
    cudaFuncSetAttribute(yblock_mma, cudaFuncAttributeMaxDynamicSharedMemorySize, YB_SMEM);

    // launch order: gemm1 is 4th (ncu captures it)
    hparams_kernel<<<1, 128>>>(A_log, dtb);                                   // 1
    to_half_kernel<<<1184, 256>>>(W_in,   w1h_ptr,  (IN2 * DMODEL) / 8);      // 2
    to_half_kernel<<<1184, 256>>>(hidden, hidh_ptr, (L_TOK * DMODEL) / 8);    // 3

    // GEMM1: xz[L, IN2] = hid @ W_in^T
    {
        int tiles_m = L_TOK / 128;
        int tiles_n = IN2 / 256;
        gemm_mma<<<tiles_m * tiles_n, 512, GM_SMEM>>>(hidh_ptr, w1h_ptr, xz_ptr,
                                                      L_TOK, IN2, DMODEL, tiles_m);  // 4
    }

    gemmG_kernel<<<dim3(NCHUNK, NG), 256>>>(Bin, Cin);                        // 5
    states_kernel<<<dim3(NCHUNK, NH), 256>>>(Bin);                            // 6
    scan_kernel<<<NH, 256>>>();                                               // 7
    yblock_mma<<<dim3(NCHUNK, NH), 256, YB_SMEM>>>(Cin, Dv);                  // 8

    to_half_kernel<<<1184, 256>>>(W_out, w2h_ptr, (DMODEL * INNER) / 8);      // 9

    // GEMM2: out = yg @ W_out^T
    {
        int tiles_m = L_TOK / 128;
        int tiles_n = DMODEL / 256;
        gemm_mma<<<tiles_m * tiles_n, 512, GM_SMEM>>>(ygh_ptr, w2h_ptr, out,
                                                      L_TOK, DMODEL, INNER, tiles_m); // 10
    }
}

// round 17
// speedup vs baseline: 1.1913x; 1.1222x over previous
#include <cuda_runtime.h>
#include <cuda_fp16.h>
#include <math.h>
#include <stdint.h>

// ---------------- problem constants ----------------
#define L_TOK   4096
#define DMODEL  3584
#define NH      112
#define HD      64
#define DS      64
#define CHUNKSZ 128
#define NCHUNK  32
#define NG      2
#define HPG     (NH / NG)          // 56
#define INNER   (NH * HD)          // 7168
#define IN2     (2 * INNER)        // 14336

// ---------------- scratch (device globals; no cudaMalloc allowed) ----------
__device__ float  g_xz[(size_t)L_TOK * IN2];           // [x | z]  (fp32)
__device__ __half g_ygh[(size_t)L_TOK * INNER];        // gated y  (fp16)
__device__ float  g_states[(size_t)NCHUNK * NH * HD * DS];  // [k][h][p][n]
__device__ __align__(16) __half g_prevh[(size_t)NCHUNK * NH * HD * DS]; // fp16 [p][n]
__device__ __align__(16) __half g_G[(size_t)NCHUNK * NG * CHUNKSZ * CHUNKSZ];
__device__ __half g_hidh[(size_t)L_TOK * DMODEL];
__device__ __half g_w1h[(size_t)IN2 * DMODEL];
__device__ __half g_w2h[(size_t)DMODEL * INNER];
__device__ float  g_dt[NH];
__device__ float  g_a[NH];

// ---------------- helpers ---------------------------------------------------
__device__ __forceinline__ uint32_t s2u(const void* p) {
    uint32_t a;
    asm("{ .reg .u64 t; cvta.to.shared.u64 t, %1; cvt.u32.u64 %0, t; }"
        : "=r"(a) : "l"(p));
    return a;
}
__device__ __forceinline__ void cpasync16(uint32_t saddr, const void* g) {
    asm volatile("cp.async.cg.shared.global [%0], [%1], 16;" :: "r"(saddr), "l"(g));
}
__device__ __forceinline__ void ldsm4(uint32_t* r, uint32_t addr) {
    asm volatile("ldmatrix.sync.aligned.m8n8.x4.shared.b16 {%0,%1,%2,%3}, [%4];"
                 : "=r"(r[0]), "=r"(r[1]), "=r"(r[2]), "=r"(r[3]) : "r"(addr));
}
__device__ __forceinline__ void mma16n8k16(float* d, const uint32_t* a,
                                           uint32_t b0, uint32_t b1) {
    asm volatile(
        "mma.sync.aligned.m16n8k16.row.col.f32.f16.f16.f32 "
        "{%0,%1,%2,%3}, {%4,%5,%6,%7}, {%8,%9}, {%0,%1,%2,%3};"
        : "+f"(d[0]), "+f"(d[1]), "+f"(d[2]), "+f"(d[3])
        : "r"(a[0]), "r"(a[1]), "r"(a[2]), "r"(a[3]), "r"(b0), "r"(b1));
}
__device__ __forceinline__ uint32_t pack_h2(float lo, float hi) {
    uint32_t r;
    asm("cvt.rn.f16x2.f32 %0, %1, %2;" : "=r"(r) : "f"(hi), "f"(lo));
    return r;
}

// ---------------- per-head parameters --------------------------------------
__global__ void hparams_kernel(const float* __restrict__ A_log,
                               const float* __restrict__ dt_bias) {
    int h = threadIdx.x;
    if (h < NH) {
        float xv = 0.1f + dt_bias[h];
        float sp = (xv > 20.f) ? xv : log1pf(expf(xv));
        g_dt[h] = sp;
        g_a[h]  = -expf(A_log[h]) * sp;
    }
}

// ---------------- fp32 -> fp16 conversion ----------------------------------
__global__ void to_half_kernel(const float* __restrict__ in, __half* __restrict__ out, int n8) {
    int i = blockIdx.x * blockDim.x + threadIdx.x;
    int stride = gridDim.x * blockDim.x;
    for (; i < n8; i += stride) {
        float4 a = ((const float4*)in)[2 * i];
        float4 b = ((const float4*)in)[2 * i + 1];
        uint4 o;
        o.x = pack_h2(a.x, a.y);
        o.y = pack_h2(a.z, a.w);
        o.z = pack_h2(b.x, b.y);
        o.w = pack_h2(b.z, b.w);
        ((uint4*)out)[i] = o;
    }
}

// ---------------- FP16 GEMM (R10 proven): 128x256x64, 512 thr, 4-stage -----
#define KTH      64
#define ALDH     72
#define A_H      (128 * ALDH)
#define B_H      (256 * ALDH)
#define STGB     ((A_H + B_H) * 2)           // 55296 B
#define NSTG     4
#define GM_SMEM  (NSTG * STGB)               // 221184 B

__global__ __launch_bounds__(512, 1)
void gemm_mma(const __half* __restrict__ A, const __half* __restrict__ B,
              float* __restrict__ C, int M, int N, int K, int tiles_m) {
    extern __shared__ __align__(16) char smraw[];
    uint32_t sbase = s2u(smraw);

    int tid = threadIdx.x, lane = tid & 31, wid = tid >> 5;
    int wm = (wid & 1) * 64;
    int wn = (wid >> 1) * 32;
    int bid = blockIdx.x;
    int m0 = (bid % tiles_m) * 128;
    int n0 = (bid / tiles_m) * 256;

    const __half* gA[2]; uint32_t oA[2];
    #pragma unroll
    for (int it = 0; it < 2; it++) {
        int q = tid + it * 512;
        int r = q >> 3, c8 = (q & 7) * 8;
        gA[it] = A + (size_t)(m0 + r) * K + c8;
        oA[it] = (uint32_t)(r * ALDH + c8) * 2;
    }
    const __half* gB[4]; uint32_t oB[4];
    #pragma unroll
    for (int it = 0; it < 4; it++) {
        int q = tid + it * 512;
        int r = q >> 3, c8 = (q & 7) * 8;
        gB[it] = B + (size_t)(n0 + r) * K + c8;
        oB[it] = (uint32_t)(A_H + r * ALDH + c8) * 2;
    }

    int lr = lane & 7;
    int a_row = lr + ((lane >> 3) & 1) * 8;
    int a_col = ((lane >> 4) & 1) * 8;
    uint32_t aoff[4];
    #pragma unroll
    for (int t = 0; t < 4; t++)
        aoff[t] = sbase + (uint32_t)(((wm + t * 16 + a_row) * ALDH + a_col) * 2);
    int b_row = lr + ((lane >> 4) & 1) * 8;
    int b_col = ((lane >> 3) & 1) * 8;
    uint32_t boff[2];
    #pragma unroll
    for (int v = 0; v < 2; v++)
        boff[v] = sbase + (uint32_t)((A_H + (wn + v * 16 + b_row) * ALDH + b_col) * 2);

    const int NKC = K / KTH;

    #pragma unroll
    for (int s = 0; s < NSTG - 1; s++) {
        uint32_t sb = sbase + s * STGB;
        #pragma unroll
        for (int it = 0; it < 2; it++) cpasync16(sb + oA[it], gA[it] + s * KTH);
        #pragma unroll
        for (int it = 0; it < 4; it++) cpasync16(sb + oB[it], gB[it] + s * KTH);
        asm volatile("cp.async.commit_group;");
    }

    float acc[4][4][4];
    #pragma unroll
    for (int t = 0; t < 4; t++)
        #pragma unroll
        for (int u = 0; u < 4; u++)
            #pragma unroll
            for (int v = 0; v < 4; v++) acc[t][u][v] = 0.f;

    for (int kb = 0; kb < NKC; kb++) {
        int st = kb & (NSTG - 1);
        asm volatile("cp.async.wait_group %0;" :: "n"(NSTG - 2));
        __syncthreads();
        {
            int fc = kb + NSTG - 1;
            if (fc < NKC) {
                uint32_t sb = sbase + (fc & (NSTG - 1)) * STGB;
                #pragma unroll
                for (int it = 0; it < 2; it++) cpasync16(sb + oA[it], gA[it] + fc * KTH);
                #pragma unroll
                for (int it = 0; it < 4; it++) cpasync16(sb + oB[it], gB[it] + fc * KTH);
            }
            asm volatile("cp.async.commit_group;");
        }
        uint32_t stb = st * STGB;
        #pragma unroll
        for (int ks = 0; ks < 4; ks++) {
            uint32_t kadd = stb + ks * 32;
            uint32_t af[4][4];
            #pragma unroll
            for (int t = 0; t < 4; t++) ldsm4(af[t], aoff[t] + kadd);
            uint32_t bf[2][4];
            #pragma unroll
            for (int v = 0; v < 2; v++) ldsm4(bf[v], boff[v] + kadd);
            #pragma unroll
            for (int u = 0; u < 4; u++) {
                uint32_t b0 = bf[u >> 1][(u & 1) * 2 + 0];
                uint32_t b1 = bf[u >> 1][(u & 1) * 2 + 1];
                #pragma unroll
                for (int t = 0; t < 4; t++) mma16n8k16(acc[t][u], af[t], b0, b1);
            }
        }
    }

    int g4 = lane >> 2, c4i = lane & 3;
    #pragma unroll
    for (int t = 0; t < 4; t++) {
        int r0 = m0 + wm + t * 16 + g4;
        #pragma unroll
        for (int u = 0; u < 4; u++) {
            int col = n0 + wn + u * 8 + c4i * 2;
            *(float2*)&C[(size_t)r0 * N + col] = make_float2(acc[t][u][0], acc[t][u][1]);
            *(float2*)&C[(size_t)(r0 + 8) * N + col] = make_float2(acc[t][u][2], acc[t][u][3]);
        }
    }
}

// ---------------- G = C @ B^T per (chunk, group), fp32 in, convert in-kernel
#define GALD 72
__global__ __launch_bounds__(256)
void gemmG_kernel(const float* __restrict__ Bin, const float* __restrict__ Cin) {
    __shared__ __align__(16) __half sC[128 * GALD];
    __shared__ __align__(16) __half sB[128 * GALD];
    int k = blockIdx.x, g = blockIdx.y;
    int tid = threadIdx.x, lane = tid & 31, wid = tid >> 5;
    int lb = k * CHUNKSZ;

    #pragma unroll
    for (int it = 0; it < 8; it++) {
        int q = tid + it * 256;
        int which = q >> 10, rem = q & 1023;
        int r = rem >> 3, c8 = (rem & 7) * 8;
        const float* src = (which ? Bin : Cin) + ((size_t)(lb + r) * NG + g) * DS + c8;
        float4 v0 = *(const float4*)src;
        float4 v1 = *(const float4*)(src + 4);
        uint4 o;
        o.x = pack_h2(v0.x, v0.y);
        o.y = pack_h2(v0.z, v0.w);
        o.z = pack_h2(v1.x, v1.y);
        o.w = pack_h2(v1.z, v1.w);
        __half* dst = (which ? sB : sC) + r * GALD + c8;
        *(uint4*)dst = o;
    }
    __syncthreads();

    uint32_t sCb = s2u(sC), sBb = s2u(sB);
    int wm = (wid & 1) * 64, wn = (wid >> 1) * 32;
    int lr = lane & 7;
    int a_row = lr + ((lane >> 3) & 1) * 8;
    int a_col = ((lane >> 4) & 1) * 8;
    uint32_t aoff[4];
    #pragma unroll
    for (int t = 0; t < 4; t++)
        aoff[t] = sCb + (uint32_t)(((wm + t * 16 + a_row) * GALD + a_col) * 2);
    int b_row = lr + ((lane >> 4) & 1) * 8;
    int b_col = ((lane >> 3) & 1) * 8;
    uint32_t boff[2];
    #pragma unroll
    for (int v = 0; v < 2; v++)
        boff[v] = sBb + (uint32_t)(((wn + v * 16 + b_row) * GALD + b_col) * 2);

    float acc[4][4][4];
    #pragma unroll
    for (int t = 0; t < 4; t++)
        #pragma unroll
        for (int u = 0; u < 4; u++)
            #pragma unroll
            for (int v = 0; v < 4; v++) acc[t][u][v] = 0.f;

    #pragma unroll
    for (int ks = 0; ks < 4; ks++) {
        uint32_t kadd = ks * 32;
        uint32_t af[4][4];
        #pragma unroll
        for (int t = 0; t < 4; t++) ldsm4(af[t], aoff[t] + kadd);
        uint32_t bf[2][4];
        #pragma unroll
        for (int v = 0; v < 2; v++) ldsm4(bf[v], boff[v] + kadd);
        #pragma unroll
        for (int u = 0; u < 4; u++) {
            uint32_t b0 = bf[u >> 1][(u & 1) * 2 + 0];
            uint32_t b1 = bf[u >> 1][(u & 1) * 2 + 1];
            #pragma unroll
            for (int t = 0; t < 4; t++) mma16n8k16(acc[t][u], af[t], b0, b1);
        }
    }

    __half* Gout = g_G + ((size_t)(k * NG + g) << 14);
    int g4 = lane >> 2, c4i = lane & 3;
    #pragma unroll
    for (int t = 0; t < 4; t++) {
        int r0 = wm + t * 16 + g4;
        #pragma unroll
        for (int u = 0; u < 4; u++) {
            int col = wn + u * 8 + c4i * 2;
            *(uint32_t*)&Gout[r0 * 128 + col] = pack_h2(acc[t][u][0], acc[t][u][1]);
            *(uint32_t*)&Gout[(r0 + 8) * 128 + col] = pack_h2(acc[t][u][2], acc[t][u][3]);
        }
    }
}

// ---------------- states via mma: S[p,n] = sum_j (w_j x[j,p]) B[j,n] -------
// Per (k,h): M=64(p), N=64(n), K=128(j). 8 warps 2m x 4n, warp tile 32x16.
#define SALD 136
__global__ __launch_bounds__(256)
void states_mma(const float* __restrict__ Bin) {
    __shared__ __align__(16) __half sXw[64 * SALD];
    __shared__ __align__(16) __half sBw[64 * SALD];
    __shared__ float sW[128];
    int k = blockIdx.x, h = blockIdx.y;
    int tid = threadIdx.x, lane = tid & 31, wid = tid >> 5;
    float a = g_a[h], dtv = g_dt[h];
    int g = h / HPG;
    int lb = k * CHUNKSZ;

    if (tid < 128) sW[tid] = dtv * expf(a * (float)(CHUNKSZ - 1 - tid));
    __syncthreads();

    // sXw[p][j] = x[j,p] * w[j]  (transpose fill, j-pairs packed)
    for (int q = tid; q < 64 * 16; q += 256) {
        int j = (q >> 4) * 2, p4 = (q & 15) * 4;
        const float* x0 = &g_xz[(size_t)(lb + j) * IN2 + h * HD + p4];
        const float* x1 = x0 + IN2;
        float4 v0 = *(const float4*)x0;
        float4 v1 = *(const float4*)x1;
        float w0 = sW[j], w1 = sW[j + 1];
        *(uint32_t*)&sXw[(p4 + 0) * SALD + j] = pack_h2(v0.x * w0, v1.x * w1);
        *(uint32_t*)&sXw[(p4 + 1) * SALD + j] = pack_h2(v0.y * w0, v1.y * w1);
        *(uint32_t*)&sXw[(p4 + 2) * SALD + j] = pack_h2(v0.z * w0, v1.z * w1);
        *(uint32_t*)&sXw[(p4 + 3) * SALD + j] = pack_h2(v0.w * w0, v1.w * w1);
    }
    // sBw[n][j] = B[j,n]  (transpose fill)
    for (int q = tid; q < 64 * 16; q += 256) {
        int j = (q >> 4) * 2, n4 = (q & 15) * 4;
        const float* b0 = &Bin[((size_t)(lb + j) * NG + g) * DS + n4];
        const float* b1 = b0 + NG * DS;
        float4 v0 = *(const float4*)b0;
        float4 v1 = *(const float4*)b1;
        *(uint32_t*)&sBw[(n4 + 0) * SALD + j] = pack_h2(v0.x, v1.x);
        *(uint32_t*)&sBw[(n4 + 1) * SALD + j] = pack_h2(v0.y, v1.y);
        *(uint32_t*)&sBw[(n4 + 2) * SALD + j] = pack_h2(v0.z, v1.z);
        *(uint32_t*)&sBw[(n4 + 3) * SALD + j] = pack_h2(v0.w, v1.w);
    }
    __syncthreads();

    uint32_t sXb = s2u(sXw), sBb = s2u(sBw);
    int wm = (wid & 1) * 32, wn = (wid >> 1) * 16;
    int lr = lane & 7;
    int a_row = lr + ((lane >> 3) & 1) * 8;
    int a_col = ((lane >> 4) & 1) * 8;
    uint32_t aoff[2];
    #pragma unroll
    for (int t = 0; t < 2; t++)
        aoff[t] = sXb + (uint32_t)(((wm + t * 16 + a_row) * SALD + a_col) * 2);
    int b_row = lr + ((lane >> 4) & 1) * 8;
    int b_col = ((lane >> 3) & 1) * 8;
    uint32_t boff = sBb + (uint32_t)(((wn + b_row) * SALD + b_col) * 2);

    float acc[2][2][4];
    #pragma unroll
    for (int t = 0; t < 2; t++)
        #pragma unroll
        for (int u = 0; u < 2; u++)
            #pragma unroll
            for (int v = 0; v < 4; v++) acc[t][u][v] = 0.f;

    #pragma unroll
    for (int ks = 0; ks < 8; ks++) {
        uint32_t kadd = ks * 32;            // 16 halfs per k-step
        uint32_t af[2][4];
        #pragma unroll
        for (int t = 0; t < 2; t++) ldsm4(af[t], aoff[t] + kadd);
        uint32_t bf[4];
        ldsm4(bf, boff + kadd);
        #pragma unroll
        for (int u = 0; u < 2; u++) {
            uint32_t b0 = bf[u * 2 + 0];
            uint32_t b1 = bf[u * 2 + 1];
            #pragma unroll
            for (int t = 0; t < 2; t++) mma16n8k16(acc[t][u], af[t], b0, b1);
        }
    }

    size_t base = ((size_t)(k * NH + h)) << 12;
    int g4 = lane >> 2, c4i = lane & 3;
    #pragma unroll
    for (int t = 0; t < 2; t++) {
        #pragma unroll
        for (int half_ = 0; half_ < 2; half_++) {
            int p = wm + t * 16 + g4 + half_ * 8;
            #pragma unroll
            for (int u = 0; u < 2; u++) {
                int n = wn + u * 8 + c4i * 2;
                *(float2*)&g_states[base + p * 64 + n] =
                    make_float2(acc[t][u][half_ * 2 + 0], acc[t][u][half_ * 2 + 1]);
            }
        }
    }
}

// ---------------- inter-chunk scan (fp16 prev out, [p][n]) ------------------
__global__ void scan_kernel() {
    int h = blockIdx.x;
    float cd = expf(g_a[h] * (float)CHUNKSZ);
    for (int e = threadIdx.x; e < HD * DS; e += 256) {
        float carry = 0.f;
        #pragma unroll
        for (int k = 0; k < NCHUNK; k++) {
            size_t base = ((size_t)(k * NH + h)) << 12;
            g_prevh[base + e] = __float2half(carry);
            carry = carry * cd + g_states[base + e];
        }
    }
}

// ---------------- yblock: Y = [G' | C*exp] @ [X^T | prev]^T via mma ---------
#define KTOT 192
#define ALD2 200
#define YB_SMEM ((128 * ALD2 + 64 * ALD2) * 2 + 132 * 4)

__global__ __launch_bounds__(256, 2)
void yblock_mma(const float* __restrict__ Cin, const float* __restrict__ Dv) {
    extern __shared__ __align__(16) char sraw[];
    __half* sA  = (__half*)sraw;               // [128][ALD2]
    __half* sBt = sA + 128 * ALD2;             // [64][ALD2]
    float* sDec = (float*)(sBt + 64 * ALD2);   // [132]

    int k = blockIdx.x, h = blockIdx.y;
    int tid = threadIdx.x, lane = tid & 31, wid = tid >> 5;
    float a = g_a[h], dtv = g_dt[h], Dh = Dv[h];
    int g = h / HPG;
    int lb = k * CHUNKSZ;

    for (int d = tid; d < 130; d += 256) sDec[d] = expf(a * (float)d);
    __syncthreads();

    {
        const __half* Gh = g_G + ((size_t)(k * NG + g) << 14);
        for (int q = tid; q < 128 * 64; q += 256) {
            int i = q >> 6, j2 = (q & 63) * 2;
            __half2 gv = *(const __half2*)&Gh[i * 128 + j2];
            float2 f = __half22float2(gv);
            float w0 = (j2 <= i) ? f.x * dtv * sDec[i - j2] : 0.f;
            float w1 = (j2 + 1 <= i) ? f.y * dtv * sDec[i - j2 - 1] : 0.f;
            *(uint32_t*)&sA[i * ALD2 + j2] = pack_h2(w0, w1);
        }
    }
    for (int q = tid; q < 128 * 16; q += 256) {
        int i = q >> 4, n4 = (q & 15) * 4;
        float4 c = *(const float4*)&Cin[((size_t)(lb + i) * NG + g) * DS + n4];
        float sc = sDec[i + 1];
        uint2 o;
        o.x = pack_h2(c.x * sc, c.y * sc);
        o.y = pack_h2(c.z * sc, c.w * sc);
        *(uint2*)&sA[i * ALD2 + 128 + n4] = o;
    }
    for (int q = tid; q < 64 * 16; q += 256) {
        int j = (q >> 4) * 2, p4 = (q & 15) * 4;
        const float* x0 = &g_xz[(size_t)(lb + j) * IN2 + h * HD + p4];
        const float* x1 = x0 + IN2;
        float4 v0 = *(const float4*)x0;
        float4 v1 = *(const float4*)x1;
        *(uint32_t*)&sBt[(p4 + 0) * ALD2 + j] = pack_h2(v0.x, v1.x);
        *(uint32_t*)&sBt[(p4 + 1) * ALD2 + j] = pack_h2(v0.y, v1.y);
        *(uint32_t*)&sBt[(p4 + 2) * ALD2 + j] = pack_h2(v0.z, v1.z);
        *(uint32_t*)&sBt[(p4 + 3) * ALD2 + j] = pack_h2(v0.w, v1.w);
    }
    {
        const uint4* Pv = (const uint4*)(g_prevh + ((size_t)(k * NH + h) << 12));
        for (int q = tid; q < 512; q += 256) {
            int p = q >> 3, c8 = (q & 7) * 8;
            *(uint4*)&sBt[p * ALD2 + 128 + c8] = Pv[q];
        }
    }
    __syncthreads();

    uint32_t sAb = s2u(sA), sBb = s2u(sBt);
    int wm = (wid & 1) * 64, wn = (wid >> 1) * 16;
    int lr = lane & 7;
    int a_row = lr + ((lane >> 3) & 1) * 8;
    int a_col = ((lane >> 4) & 1) * 8;
    uint32_t aoff[4];
    #pragma unroll
    for (int t = 0; t < 4; t++)
        aoff[t] = sAb + (uint32_t)(((wm + t * 16 + a_row) * ALD2 + a_col) * 2);
    int b_row = lr + ((lane >> 4) & 1) * 8;
    int b_col = ((lane >> 3) & 1) * 8;
    uint32_t boff = sBb + (uint32_t)(((wn + b_row) * ALD2 + b_col) * 2);

    float acc[4][2][4];
    #pragma unroll
    for (int t = 0; t < 4; t++)
        #pragma unroll
        for (int u = 0; u < 2; u++)
            #pragma unroll
            for (int v = 0; v < 4; v++) acc[t][u][v] = 0.f;

    #pragma unroll
    for (int ks = 0; ks < KTOT / 16; ks++) {
        uint32_t kadd = ks * 32;
        uint32_t af[4][4];
        #pragma unroll
        for (int t = 0; t < 4; t++) ldsm4(af[t], aoff[t] + kadd);
        uint32_t bf[4];
        ldsm4(bf, boff + kadd);
        #pragma unroll
        for (int u = 0; u < 2; u++) {
            uint32_t b0 = bf[u * 2 + 0];
            uint32_t b1 = bf[u * 2 + 1];
            #pragma unroll
            for (int t = 0; t < 4; t++) mma16n8k16(acc[t][u], af[t], b0, b1);
        }
    }

    int g4 = lane >> 2, c4i = lane & 3;
    #pragma unroll
    for (int t = 0; t < 4; t++) {
        #pragma unroll
        for (int half_ = 0; half_ < 2; half_++) {
            int i = wm + t * 16 + g4 + half_ * 8;
            int l = lb + i;
            #pragma unroll
            for (int u = 0; u < 2; u++) {
                int p = wn + u * 8 + c4i * 2;
                float y0 = acc[t][u][half_ * 2 + 0];
                float y1 = acc[t][u][half_ * 2 + 1];
                float x0 = __half2float(sBt[p * ALD2 + i]);
                float x1 = __half2float(sBt[(p + 1) * ALD2 + i]);
                float2 zv = *(const float2*)&g_xz[(size_t)l * IN2 + INNER + h * HD + p];
                y0 = (y0 + x0 * Dh) / (1.f + expf(-zv.x));
                y1 = (y1 + x1 * Dh) / (1.f + expf(-zv.y));
                *(uint32_t*)&g_ygh[(size_t)l * INNER + h * HD + p] = pack_h2(y0, y1);
            }
        }
    }
}

// ---------------- launcher --------------------------------------------------
extern "C" void kernel_launch(void* const* d_in, const int* in_sizes, int n_in,
                              void* d_out, int out_size) {
    (void)in_sizes; (void)n_in; (void)out_size;
    const float* hidden = (const float*)d_in[0];
    const float* W_in   = (const float*)d_in[1];
    const float* W_out  = (const float*)d_in[2];
    const float* A_log  = (const float*)d_in[3];
    const float* Dv     = (const float*)d_in[4];
    const float* dtb    = (const float*)d_in[5];
    const float* Bin    = (const float*)d_in[6];
    const float* Cin    = (const float*)d_in[7];
    float* out = (float*)d_out;

    float *xz_ptr;
    __half *ygh_ptr, *hidh_ptr, *w1h_ptr, *w2h_ptr;
    cudaGetSymbolAddress((void**)&xz_ptr, g_xz);
    cudaGetSymbolAddress((void**)&ygh_ptr, g_ygh);
    cudaGetSymbolAddress((void**)&hidh_ptr, g_hidh);
    cudaGetSymbolAddress((void**)&w1h_ptr, g_w1h);
    cudaGetSymbolAddress((void**)&w2h_ptr, g_w2h);

    cudaFuncSetAttribute(gemm_mma, cudaFuncAttributeMaxDynamicSharedMemorySize, GM_SMEM);
    cudaFuncSetAttribute(yblock_mma, cudaFuncAttributeMaxDynamicSharedMemorySize, YB_SMEM);

    // launch order: gemm1 is 4th (ncu captures it)
    hparams_kernel<<<1, 128>>>(A_log, dtb);                                   // 1
    to_half_kernel<<<1184, 256>>>(W_in,   w1h_ptr,  (IN2 * DMODEL) / 8);      // 2
    to_half_kernel<<<1184, 256>>>(hidden, hidh_ptr, (L_TOK * DMODEL) / 8);    // 3

    // GEMM1: xz[L, IN2] = hid @ W_in^T
    {
        int tiles_m = L_TOK / 128;
        int tiles_n = IN2 / 256;
        gemm_mma<<<tiles_m * tiles_n, 512, GM_SMEM>>>(hidh_ptr, w1h_ptr, xz_ptr,
                                                      L_TOK, IN2, DMODEL, tiles_m);  // 4
    }

    gemmG_kernel<<<dim3(NCHUNK, NG), 256>>>(Bin, Cin);                        // 5
    states_mma<<<dim3(NCHUNK, NH), 256>>>(Bin);                               // 6
    scan_kernel<<<NH, 256>>>();                                               // 7
    yblock_mma<<<dim3(NCHUNK, NH), 256, YB_SMEM>>>(Cin, Dv);                  // 8

    to_half_kernel<<<1184, 256>>>(W_out, w2h_ptr, (DMODEL * INNER) / 8);      // 9

    // GEMM2: out = yg @ W_out^T
    {
        int tiles_m = L_TOK / 128;
        int tiles_n = DMODEL / 256;
        gemm_mma<<<tiles_m * tiles_n, 512, GM_SMEM>>>(ygh_ptr, w2h_ptr, out,
                                                      L_TOK, DMODEL, INNER, tiles_m); // 10
    }
}